// round 2
// baseline (speedup 1.0000x reference)
#include <cuda_runtime.h>

// Problem constants
#define B_    2
#define S_    1024
#define D_    1024
#define H_    16
#define DH_   64
#define BH_   (B_*H_)      // 32
#define ROWS_ (B_*S_)      // 2048
#define SS_   (S_*S_)      // 1048576

// Scratch (static device globals -- allocation-free rule)
__device__ float g_q [BH_*S_*DH_];
__device__ float g_k [BH_*S_*DH_];
__device__ float g_v [BH_*S_*DH_];
__device__ float g_qr[BH_*S_*DH_];
__device__ float g_kr[BH_*S_*DH_];
__device__ float g_c2c[BH_*SS_];   // later holds combined scores / probs
__device__ float g_c2p[BH_*SS_];
__device__ float g_p2c[BH_*SS_];
__device__ float g_ctx[ROWS_*D_];

#define NEG_INF __int_as_float(0xff800000)

// ---------------------------------------------------------------------------
// Projections: 5 GEMMs (2048x1024) @ (1024x1024)^T fused via blockIdx.z.
// NT layout: C[r,n] = sum_k A[r,k] * W[n,k] + bias[n]
// Output written in (b, h, s, d) head-major layout.
// ---------------------------------------------------------------------------
__global__ __launch_bounds__(256) void proj_kernel(
    const float* __restrict__ x,  const float* __restrict__ rel,
    const float* __restrict__ Wq, const float* __restrict__ bq,
    const float* __restrict__ Wk, const float* __restrict__ bk,
    const float* __restrict__ Wv, const float* __restrict__ bv,
    const float* __restrict__ Wqr,const float* __restrict__ bqr,
    const float* __restrict__ Wkr,const float* __restrict__ bkr)
{
    const float* A; const float* W; const float* bias; float* O;
    switch (blockIdx.z) {
        case 0:  A = x;   W = Wq;  bias = bq;  O = g_q;  break;
        case 1:  A = x;   W = Wk;  bias = bk;  O = g_k;  break;
        case 2:  A = x;   W = Wv;  bias = bv;  O = g_v;  break;
        case 3:  A = rel; W = Wqr; bias = bqr; O = g_qr; break;
        default: A = rel; W = Wkr; bias = bkr; O = g_kr; break;
    }

    __shared__ float As[8][128];
    __shared__ float Bs[8][128];

    const int tid  = threadIdx.x;
    const int brow = blockIdx.y * 128;
    const int bcol = blockIdx.x * 128;
    const int lr   = tid >> 1;            // 0..127
    const int lc   = (tid & 1) * 4;       // 0 or 4
    const int tr   = (tid >> 4) * 8;      // 0..120
    const int tc   = (tid & 15) * 8;      // 0..120

    float acc[8][8];
#pragma unroll
    for (int i = 0; i < 8; i++)
#pragma unroll
        for (int j = 0; j < 8; j++) acc[i][j] = 0.f;

    const float* Aptr = A + (brow + lr) * D_ + lc;
    const float* Wptr = W + (bcol + lr) * D_ + lc;

    for (int k0 = 0; k0 < D_; k0 += 8) {
        float4 a4 = *(const float4*)(Aptr + k0);
        float4 b4 = *(const float4*)(Wptr + k0);
        As[lc + 0][lr] = a4.x; As[lc + 1][lr] = a4.y;
        As[lc + 2][lr] = a4.z; As[lc + 3][lr] = a4.w;
        Bs[lc + 0][lr] = b4.x; Bs[lc + 1][lr] = b4.y;
        Bs[lc + 2][lr] = b4.z; Bs[lc + 3][lr] = b4.w;
        __syncthreads();
#pragma unroll
        for (int kk = 0; kk < 8; kk++) {
            float a[8], b[8];
            *(float4*)(a)     = *(const float4*)&As[kk][tr];
            *(float4*)(a + 4) = *(const float4*)&As[kk][tr + 4];
            *(float4*)(b)     = *(const float4*)&Bs[kk][tc];
            *(float4*)(b + 4) = *(const float4*)&Bs[kk][tc + 4];
#pragma unroll
            for (int i = 0; i < 8; i++)
#pragma unroll
                for (int j = 0; j < 8; j++)
                    acc[i][j] += a[i] * b[j];
        }
        __syncthreads();
    }

#pragma unroll
    for (int i = 0; i < 8; i++) {
        const int r  = brow + tr + i;
        const int bb = r >> 10;
        const int s  = r & (S_ - 1);
#pragma unroll
        for (int j = 0; j < 8; j++) {
            const int n = bcol + tc + j;
            const int h = n >> 6;
            const int d = n & 63;
            O[((bb * H_ + h) * S_ + s) * DH_ + d] = acc[i][j] + bias[n];
        }
    }
}

// ---------------------------------------------------------------------------
// Final projection: out = ctx @ Wc^T + bc  (2048x1024) (1024x1024)
// ---------------------------------------------------------------------------
__global__ __launch_bounds__(256) void final_kernel(
    const float* __restrict__ Wc, const float* __restrict__ bc,
    float* __restrict__ out)
{
    __shared__ float As[8][128];
    __shared__ float Bs[8][128];

    const int tid  = threadIdx.x;
    const int brow = blockIdx.y * 128;
    const int bcol = blockIdx.x * 128;
    const int lr   = tid >> 1;
    const int lc   = (tid & 1) * 4;
    const int tr   = (tid >> 4) * 8;
    const int tc   = (tid & 15) * 8;

    float acc[8][8];
#pragma unroll
    for (int i = 0; i < 8; i++)
#pragma unroll
        for (int j = 0; j < 8; j++) acc[i][j] = 0.f;

    const float* Aptr = g_ctx + (brow + lr) * D_ + lc;
    const float* Wptr = Wc    + (bcol + lr) * D_ + lc;

    for (int k0 = 0; k0 < D_; k0 += 8) {
        float4 a4 = *(const float4*)(Aptr + k0);
        float4 b4 = *(const float4*)(Wptr + k0);
        As[lc + 0][lr] = a4.x; As[lc + 1][lr] = a4.y;
        As[lc + 2][lr] = a4.z; As[lc + 3][lr] = a4.w;
        Bs[lc + 0][lr] = b4.x; Bs[lc + 1][lr] = b4.y;
        Bs[lc + 2][lr] = b4.z; Bs[lc + 3][lr] = b4.w;
        __syncthreads();
#pragma unroll
        for (int kk = 0; kk < 8; kk++) {
            float a[8], b[8];
            *(float4*)(a)     = *(const float4*)&As[kk][tr];
            *(float4*)(a + 4) = *(const float4*)&As[kk][tr + 4];
            *(float4*)(b)     = *(const float4*)&Bs[kk][tc];
            *(float4*)(b + 4) = *(const float4*)&Bs[kk][tc + 4];
#pragma unroll
            for (int i = 0; i < 8; i++)
#pragma unroll
                for (int j = 0; j < 8; j++)
                    acc[i][j] += a[i] * b[j];
        }
        __syncthreads();
    }

#pragma unroll
    for (int i = 0; i < 8; i++) {
        const int r = brow + tr + i;
#pragma unroll
        for (int j = 0; j < 8; j++) {
            const int n = bcol + tc + j;
            out[r * D_ + n] = acc[i][j] + bc[n];
        }
    }
}

// ---------------------------------------------------------------------------
// Score GEMMs: per (b,h): c2c = Q K^T, c2p_att = Q KR^T, p2c_att = QR K^T.
// Each (1024x64)(1024x64)^T -> (1024x1024). blockIdx.z = bh*3 + which.
// ---------------------------------------------------------------------------
__global__ __launch_bounds__(256) void scores_kernel()
{
    const int z     = blockIdx.z;
    const int bh    = z / 3;
    const int which = z - bh * 3;

    const float* Qb  = g_q  + bh * S_ * DH_;
    const float* Kb  = g_k  + bh * S_ * DH_;
    const float* QRb = g_qr + bh * S_ * DH_;
    const float* KRb = g_kr + bh * S_ * DH_;

    const float* A; const float* Bm; float* O;
    if (which == 0)      { A = Qb;  Bm = Kb;  O = g_c2c + bh * SS_; }
    else if (which == 1) { A = Qb;  Bm = KRb; O = g_c2p + bh * SS_; }
    else                 { A = QRb; Bm = Kb;  O = g_p2c + bh * SS_; }

    __shared__ float As[8][128];
    __shared__ float Bs[8][128];

    const int tid  = threadIdx.x;
    const int brow = blockIdx.y * 128;
    const int bcol = blockIdx.x * 128;
    const int lr   = tid >> 1;
    const int lc   = (tid & 1) * 4;
    const int tr   = (tid >> 4) * 8;
    const int tc   = (tid & 15) * 8;

    float acc[8][8];
#pragma unroll
    for (int i = 0; i < 8; i++)
#pragma unroll
        for (int j = 0; j < 8; j++) acc[i][j] = 0.f;

    const float* Aptr = A  + (brow + lr) * DH_ + lc;
    const float* Bptr = Bm + (bcol + lr) * DH_ + lc;

    for (int k0 = 0; k0 < DH_; k0 += 8) {
        float4 a4 = *(const float4*)(Aptr + k0);
        float4 b4 = *(const float4*)(Bptr + k0);
        As[lc + 0][lr] = a4.x; As[lc + 1][lr] = a4.y;
        As[lc + 2][lr] = a4.z; As[lc + 3][lr] = a4.w;
        Bs[lc + 0][lr] = b4.x; Bs[lc + 1][lr] = b4.y;
        Bs[lc + 2][lr] = b4.z; Bs[lc + 3][lr] = b4.w;
        __syncthreads();
#pragma unroll
        for (int kk = 0; kk < 8; kk++) {
            float a[8], b[8];
            *(float4*)(a)     = *(const float4*)&As[kk][tr];
            *(float4*)(a + 4) = *(const float4*)&As[kk][tr + 4];
            *(float4*)(b)     = *(const float4*)&Bs[kk][tc];
            *(float4*)(b + 4) = *(const float4*)&Bs[kk][tc + 4];
#pragma unroll
            for (int i = 0; i < 8; i++)
#pragma unroll
                for (int j = 0; j < 8; j++)
                    acc[i][j] += a[i] * b[j];
        }
        __syncthreads();
    }

#pragma unroll
    for (int i = 0; i < 8; i++) {
        const int r = brow + tr + i;
#pragma unroll
        for (int j = 0; j < 8; j++) {
            O[r * S_ + bcol + tc + j] = acc[i][j];
        }
    }
}

// ---------------------------------------------------------------------------
// Combine: scores = (c2c + c2p_att[i, p(i,j)] + p2c_att[p(i,j), j]) / scale
//          with p(i,j) = clamp(i - j + 512, 0, 1023), then padding mask.
// 32x32 tile per block; gathers served from a 63-wide banded shared tile.
// p2cS pitch is exactly 32 so the anti-diagonal gather has lane stride -31
// (coprime with 32) -> bank-conflict-free.
// ---------------------------------------------------------------------------
__global__ __launch_bounds__(256) void combine_kernel(const int* __restrict__ mask)
{
    const int bh = blockIdx.z;
    const int b  = bh >> 4;
    const int i0 = blockIdx.y * 32;
    const int j0 = blockIdx.x * 32;
    const int off = bh * SS_;

    __shared__ float c2pS[32][64];  // [i_local][t]
    __shared__ float p2cS[63][32];  // [t][j_local], pitch 32 (intentional)

    const int base = i0 - j0 - 31 + 512;   // p_raw = base + t, t = il - jl + 31
    const int tid  = threadIdx.x;

    for (int idx = tid; idx < 32 * 63; idx += 256) {
        const int il = idx / 63;
        const int t  = idx - il * 63;
        const int p  = min(max(base + t, 0), S_ - 1);
        c2pS[il][t] = g_c2p[off + (i0 + il) * S_ + p];
    }
    for (int idx = tid; idx < 63 * 32; idx += 256) {
        const int t  = idx >> 5;
        const int jl = idx & 31;
        const int p  = min(max(base + t, 0), S_ - 1);
        p2cS[t][jl] = g_p2c[off + p * S_ + (j0 + jl)];
    }
    __syncthreads();

    const float invScale = 0.07216878364870323f;  // 1/sqrt(3*64)
    const int jl = tid & 31;
    const int wm = mask[b * S_ + j0 + jl];

#pragma unroll
    for (int pass = 0; pass < 4; pass++) {
        const int il = pass * 8 + (tid >> 5);
        const int t  = il - jl + 31;
        const int idx = off + (i0 + il) * S_ + j0 + jl;
        float sv = (g_c2c[idx] + c2pS[il][t] + p2cS[t][jl]) * invScale;
        if (wm) sv = NEG_INF;
        g_c2c[idx] = sv;
    }
}

// ---------------------------------------------------------------------------
// Row softmax, in place on g_c2c. One block per row (1024 floats).
// ---------------------------------------------------------------------------
__global__ __launch_bounds__(256) void softmax_kernel()
{
    float* p = g_c2c + blockIdx.y * SS_ + blockIdx.x * S_;
    const int tid = threadIdx.x;

    float4 v = *(float4*)(p + tid * 4);
    float mx = fmaxf(fmaxf(v.x, v.y), fmaxf(v.z, v.w));
#pragma unroll
    for (int o = 16; o > 0; o >>= 1)
        mx = fmaxf(mx, __shfl_xor_sync(0xffffffffu, mx, o));

    __shared__ float smax[8], ssum[8];
    if ((tid & 31) == 0) smax[tid >> 5] = mx;
    __syncthreads();
    mx = fmaxf(fmaxf(fmaxf(smax[0], smax[1]), fmaxf(smax[2], smax[3])),
               fmaxf(fmaxf(smax[4], smax[5]), fmaxf(smax[6], smax[7])));

    v.x = __expf(v.x - mx);
    v.y = __expf(v.y - mx);
    v.z = __expf(v.z - mx);
    v.w = __expf(v.w - mx);
    float s = v.x + v.y + v.z + v.w;
#pragma unroll
    for (int o = 16; o > 0; o >>= 1)
        s += __shfl_xor_sync(0xffffffffu, s, o);
    if ((tid & 31) == 0) ssum[tid >> 5] = s;
    __syncthreads();
    s = ssum[0] + ssum[1] + ssum[2] + ssum[3] +
        ssum[4] + ssum[5] + ssum[6] + ssum[7];

    const float inv = 1.0f / s;
    v.x *= inv; v.y *= inv; v.z *= inv; v.w *= inv;
    *(float4*)(p + tid * 4) = v;
}

// ---------------------------------------------------------------------------
// attn @ V: per (b,h): (1024x1024) @ (1024x64) -> ctx in (b, s, h*DH+d).
// NN GEMM, 64x64x32 tiles, 4x4 microtiles.
// ---------------------------------------------------------------------------
__global__ __launch_bounds__(256) void av_kernel()
{
    const int bh = blockIdx.y;
    const int i0 = blockIdx.x * 64;
    const float* P = g_c2c + bh * SS_;
    const float* V = g_v   + bh * S_ * DH_;

    __shared__ float Ps[32][64];  // [k][i]
    __shared__ float Vs[32][64];  // [k][d]

    const int tid = threadIdx.x;
    const int ar = tid >> 2;          // 0..63
    const int ac = (tid & 3) * 8;     // 0,8,16,24
    const int vr = tid >> 3;          // 0..31
    const int vc = (tid & 7) * 8;     // 0..56
    const int ti = (tid >> 4) * 4;    // 0..60
    const int td = (tid & 15) * 4;    // 0..60

    float acc[4][4];
#pragma unroll
    for (int i = 0; i < 4; i++)
#pragma unroll
        for (int j = 0; j < 4; j++) acc[i][j] = 0.f;

    for (int k0 = 0; k0 < S_; k0 += 32) {
        float4 a0 = *(const float4*)&P[(i0 + ar) * S_ + k0 + ac];
        float4 a1 = *(const float4*)&P[(i0 + ar) * S_ + k0 + ac + 4];
        Ps[ac + 0][ar] = a0.x; Ps[ac + 1][ar] = a0.y;
        Ps[ac + 2][ar] = a0.z; Ps[ac + 3][ar] = a0.w;
        Ps[ac + 4][ar] = a1.x; Ps[ac + 5][ar] = a1.y;
        Ps[ac + 6][ar] = a1.z; Ps[ac + 7][ar] = a1.w;
        *(float4*)&Vs[vr][vc]     = *(const float4*)&V[(k0 + vr) * DH_ + vc];
        *(float4*)&Vs[vr][vc + 4] = *(const float4*)&V[(k0 + vr) * DH_ + vc + 4];
        __syncthreads();
#pragma unroll
        for (int kk = 0; kk < 32; kk++) {
            float a[4], b[4];
            *(float4*)a = *(const float4*)&Ps[kk][ti];
            *(float4*)b = *(const float4*)&Vs[kk][td];
#pragma unroll
            for (int i = 0; i < 4; i++)
#pragma unroll
                for (int j = 0; j < 4; j++)
                    acc[i][j] += a[i] * b[j];
        }
        __syncthreads();
    }

    const int b = bh >> 4;
    const int h = bh & 15;
#pragma unroll
    for (int i = 0; i < 4; i++) {
        const int srow = i0 + ti + i;
#pragma unroll
        for (int j = 0; j < 4; j++) {
            g_ctx[(b * S_ + srow) * D_ + h * DH_ + td + j] = acc[i][j];
        }
    }
}

// ---------------------------------------------------------------------------
// Launch
// ---------------------------------------------------------------------------
extern "C" void kernel_launch(void* const* d_in, const int* in_sizes, int n_in,
                              void* d_out, int out_size)
{
    const float* x    = (const float*)d_in[0];
    const float* rel  = (const float*)d_in[1];
    const int*   mask = (const int*)  d_in[2];
    const float* Wq   = (const float*)d_in[3];
    const float* bq   = (const float*)d_in[4];
    const float* Wk   = (const float*)d_in[5];
    const float* bk   = (const float*)d_in[6];
    const float* Wv   = (const float*)d_in[7];
    const float* bv   = (const float*)d_in[8];
    const float* Wqr  = (const float*)d_in[9];
    const float* bqr  = (const float*)d_in[10];
    const float* Wkr  = (const float*)d_in[11];
    const float* bkr  = (const float*)d_in[12];
    const float* Wc   = (const float*)d_in[13];
    const float* bc   = (const float*)d_in[14];
    float* out = (float*)d_out;

    // 1. Q,K,V,QR,KR projections (fused over grid.z)
    proj_kernel<<<dim3(D_ / 128, ROWS_ / 128, 5), 256>>>(
        x, rel, Wq, bq, Wk, bk, Wv, bv, Wqr, bqr, Wkr, bkr);

    // 2. c2c / c2p_att / p2c_att batched GEMMs
    scores_kernel<<<dim3(S_ / 128, S_ / 128, BH_ * 3), 256>>>();

    // 3. Banded gather + sum + scale + mask
    combine_kernel<<<dim3(S_ / 32, S_ / 32, BH_), 256>>>(mask);

    // 4. Row softmax (in place)
    softmax_kernel<<<dim3(S_, BH_), 256>>>();

    // 5. attn @ V -> ctx (b, s, h*dh)
    av_kernel<<<dim3(S_ / 64, BH_), 256>>>();

    // 6. Output projection
    final_kernel<<<dim3(D_ / 128, ROWS_ / 128), 256>>>(Wc, bc, out);
}

// round 4
// speedup vs baseline: 2.1597x; 2.1597x over previous
#include <cuda_runtime.h>
#include <cuda_bf16.h>

// Problem constants
#define B_    2
#define S_    1024
#define D_    1024
#define H_    16
#define DH_   64
#define BH_   (B_*H_)      // 32
#define ROWS_ (B_*S_)      // 2048
#define SS_   (S_*S_)      // 1048576

#define NEG_INF __int_as_float(0xff800000)

// ---------------------------------------------------------------------------
// Device-global scratch (allocation-free rule). bf16 operands split hi/lo.
// ---------------------------------------------------------------------------
__device__ __align__(16) __nv_bfloat16 g_xh [ROWS_*D_], g_xl [ROWS_*D_];
__device__ __align__(16) __nv_bfloat16 g_relh[ROWS_*D_], g_rell[ROWS_*D_];
__device__ __align__(16) __nv_bfloat16 g_Wh[6][D_*D_],  g_Wl[6][D_*D_]; // q,k,v,qr,kr,c

__device__ __align__(16) __nv_bfloat16 g_qh [BH_*S_*DH_], g_ql [BH_*S_*DH_];
__device__ __align__(16) __nv_bfloat16 g_kh [BH_*S_*DH_], g_kl [BH_*S_*DH_];
__device__ __align__(16) __nv_bfloat16 g_qrh[BH_*S_*DH_], g_qrl[BH_*S_*DH_];
__device__ __align__(16) __nv_bfloat16 g_krh[BH_*S_*DH_], g_krl[BH_*S_*DH_];
__device__ __align__(16) __nv_bfloat16 g_vTh[BH_*DH_*S_], g_vTl[BH_*DH_*S_]; // [bh][d][s]

__device__ __align__(16) float g_c2c[BH_*SS_];
__device__ __align__(16) float g_c2p[BH_*SS_];
__device__ __align__(16) float g_p2c[BH_*SS_];

__device__ __align__(16) __nv_bfloat16 g_ph[BH_*SS_], g_pl[BH_*SS_];     // probs
__device__ __align__(16) __nv_bfloat16 g_ctxh[ROWS_*D_], g_ctxl[ROWS_*D_];

// ---------------------------------------------------------------------------
// Helpers
// ---------------------------------------------------------------------------
__device__ __forceinline__ unsigned smem_u32(const void* p) {
    unsigned a;
    asm("{ .reg .u64 t; cvta.to.shared.u64 t, %1; cvt.u32.u64 %0, t; }"
        : "=r"(a) : "l"(p));
    return a;
}

__device__ __forceinline__ void ldsm4(unsigned r[4], unsigned a) {
    asm volatile("ldmatrix.sync.aligned.m8n8.x4.shared.b16 {%0,%1,%2,%3}, [%4];"
        : "=r"(r[0]), "=r"(r[1]), "=r"(r[2]), "=r"(r[3]) : "r"(a));
}

__device__ __forceinline__ void mma_bf16(float c[4], const unsigned a[4],
                                         unsigned b0, unsigned b1) {
    asm volatile(
        "mma.sync.aligned.m16n8k16.row.col.f32.bf16.bf16.f32 "
        "{%0,%1,%2,%3}, {%4,%5,%6,%7}, {%8,%9}, {%0,%1,%2,%3};"
        : "+f"(c[0]), "+f"(c[1]), "+f"(c[2]), "+f"(c[3])
        : "r"(a[0]), "r"(a[1]), "r"(a[2]), "r"(a[3]), "r"(b0), "r"(b1));
}

__device__ __forceinline__ void split1(float a, __nv_bfloat16& h, __nv_bfloat16& l) {
    h = __float2bfloat16(a);
    l = __float2bfloat16(a - __bfloat162float(h));
}

// ---------------------------------------------------------------------------
// Operand conversion: fp32 -> hi/lo bf16.  tag selects destination.
// ---------------------------------------------------------------------------
__global__ __launch_bounds__(256) void convert_kernel(
    const float* __restrict__ src, int tag, int n4)
{
    int i = blockIdx.x * 256 + threadIdx.x;
    if (i >= n4) return;
    __nv_bfloat16 *Dh, *Dl;
    switch (tag) {
        case 0:  Dh = g_xh;   Dl = g_xl;   break;
        case 1:  Dh = g_relh; Dl = g_rell; break;
        default: Dh = g_Wh[tag - 2]; Dl = g_Wl[tag - 2]; break;
    }
    float4 v = ((const float4*)src)[i];
    __nv_bfloat16 h[4], l[4];
    split1(v.x, h[0], l[0]); split1(v.y, h[1], l[1]);
    split1(v.z, h[2], l[2]); split1(v.w, h[3], l[3]);
    *(uint2*)(Dh + i * 4) = *(uint2*)h;
    *(uint2*)(Dl + i * 4) = *(uint2*)l;
}

// ---------------------------------------------------------------------------
// HMMA GEMM core. Block = 128 x (NT*16). 256 threads = 8 warps (4m x 2n).
// Warp tile = 32 x (NT*8). K-chunk = 32. A,B are K-major bf16 hi/lo pairs.
// bf16x3: acc += Ah*Bh + Ah*Bl + Al*Bh, fp32 accumulation.
// SMEM pitch = 40 bf16 (80B): conflict-free staging + ldmatrix.
// ---------------------------------------------------------------------------
template<int NT>
__device__ __forceinline__ void gemm_core(
    const __nv_bfloat16* __restrict__ Ah, const __nv_bfloat16* __restrict__ Al, int lda,
    const __nv_bfloat16* __restrict__ Bh, const __nv_bfloat16* __restrict__ Bl, int ldb,
    int ktiles, float acc[2][NT][4])
{
    __shared__ __align__(16) __nv_bfloat16 sAh[128 * 40], sAl[128 * 40];
    __shared__ __align__(16) __nv_bfloat16 sBh[NT * 16 * 40], sBl[NT * 16 * 40];

    const int tid  = threadIdx.x;
    const int lane = tid & 31;
    const int wid  = tid >> 5;
    const int wm   = wid & 3;
    const int wn   = wid >> 2;

    const unsigned uAh = smem_u32(sAh), uAl = smem_u32(sAl);
    const unsigned uBh = smem_u32(sBh), uBl = smem_u32(sBl);

    // ldmatrix line address components (bytes)
    const unsigned aoff = (unsigned)((wm * 32 + (lane & 15)) * 80 + ((lane >> 4) << 4));
    const unsigned boff = (unsigned)((wn * (NT * 8) + (lane & 7) + ((lane >> 4) << 3)) * 80
                                     + (((lane >> 3) & 1) << 4));

    for (int kt = 0; kt < ktiles; kt++) {
        const int kbase = kt * 32;
        // stage A: 128 x 32, hi+lo
#pragma unroll
        for (int s = 0; s < 2; s++) {
            int seg = s * 256 + tid;
            int r = seg >> 2, ks = seg & 3;
            *(uint4*)(sAh + r * 40 + ks * 8) = *(const uint4*)(Ah + r * lda + kbase + ks * 8);
            *(uint4*)(sAl + r * 40 + ks * 8) = *(const uint4*)(Al + r * lda + kbase + ks * 8);
        }
        // stage B: NT*16 x 32, hi+lo
#pragma unroll
        for (int s = 0; s < NT / 4; s++) {
            int seg = s * 256 + tid;
            int r = seg >> 2, ks = seg & 3;
            *(uint4*)(sBh + r * 40 + ks * 8) = *(const uint4*)(Bh + r * ldb + kbase + ks * 8);
            *(uint4*)(sBl + r * 40 + ks * 8) = *(const uint4*)(Bl + r * ldb + kbase + ks * 8);
        }
        __syncthreads();

#pragma unroll
        for (int ks = 0; ks < 2; ks++) {
            unsigned ah[2][4], al[2][4];
#pragma unroll
            for (int mt = 0; mt < 2; mt++) {
                unsigned o = aoff + mt * 16 * 80 + ks * 32;
                ldsm4(ah[mt], uAh + o);
                ldsm4(al[mt], uAl + o);
            }
#pragma unroll
            for (int np = 0; np < NT / 2; np++) {
                unsigned o = boff + np * 16 * 80 + ks * 32;
                unsigned bh[4], bl[4];
                ldsm4(bh, uBh + o);
                ldsm4(bl, uBl + o);
#pragma unroll
                for (int mt = 0; mt < 2; mt++) {
#pragma unroll
                    for (int sub = 0; sub < 2; sub++) {
                        float* c = acc[mt][np * 2 + sub];
                        mma_bf16(c, ah[mt], bh[sub * 2], bh[sub * 2 + 1]);
                        mma_bf16(c, ah[mt], bl[sub * 2], bl[sub * 2 + 1]);
                        mma_bf16(c, al[mt], bh[sub * 2], bh[sub * 2 + 1]);
                    }
                }
            }
        }
        __syncthreads();
    }
}

// ---------------------------------------------------------------------------
// Kernel 1: projections. z: 0=Q 1=K 2=V 3=QR 4=KR.  out head-major hi/lo bf16.
// ---------------------------------------------------------------------------
__global__ __launch_bounds__(256) void proj_mma(
    const float* __restrict__ bq, const float* __restrict__ bk,
    const float* __restrict__ bv, const float* __restrict__ bqr,
    const float* __restrict__ bkr)
{
    const int z = blockIdx.z;
    const __nv_bfloat16 *Ah, *Al;
    if (z < 3) { Ah = g_xh; Al = g_xl; } else { Ah = g_relh; Al = g_rell; }
    const __nv_bfloat16* Bh = g_Wh[z];
    const __nv_bfloat16* Bl = g_Wl[z];

    __nv_bfloat16 *Dh, *Dl; const float* bias;
    switch (z) {
        case 0:  Dh = g_qh;  Dl = g_ql;  bias = bq;  break;
        case 1:  Dh = g_kh;  Dl = g_kl;  bias = bk;  break;
        case 2:  Dh = g_vTh; Dl = g_vTl; bias = bv;  break;
        case 3:  Dh = g_qrh; Dl = g_qrl; bias = bqr; break;
        default: Dh = g_krh; Dl = g_krl; bias = bkr; break;
    }

    const int brow = blockIdx.y * 128;
    const int bcol = blockIdx.x * 128;

    float acc[2][8][4] = {};
    gemm_core<8>(Ah + brow * D_, Al + brow * D_, D_,
                 Bh + bcol * D_, Bl + bcol * D_, D_, 32, acc);

    const int lane = threadIdx.x & 31, wid = threadIdx.x >> 5;
    const int wm = wid & 3, wn = wid >> 2;
    const bool vtrans = (z == 2);

#pragma unroll
    for (int mt = 0; mt < 2; mt++) {
#pragma unroll
        for (int nt = 0; nt < 8; nt++) {
            const int n = bcol + wn * 64 + nt * 8 + (lane & 3) * 2;
            const int h = n >> 6, d = n & 63;
            const float b0 = __ldg(&bias[n]), b1 = __ldg(&bias[n + 1]);
#pragma unroll
            for (int half = 0; half < 2; half++) {
                const int m = brow + wm * 32 + mt * 16 + (lane >> 2) + half * 8;
                const int bb = m >> 10, s = m & (S_ - 1);
                float v0 = acc[mt][nt][half * 2 + 0] + b0;
                float v1 = acc[mt][nt][half * 2 + 1] + b1;
                __nv_bfloat16 h0, l0, h1, l1;
                split1(v0, h0, l0); split1(v1, h1, l1);
                if (!vtrans) {
                    const int idx = ((bb * H_ + h) * S_ + s) * DH_ + d;
                    __nv_bfloat162 ph; ph.x = h0; ph.y = h1;
                    __nv_bfloat162 pl; pl.x = l0; pl.y = l1;
                    *(__nv_bfloat162*)(Dh + idx) = ph;
                    *(__nv_bfloat162*)(Dl + idx) = pl;
                } else {
                    const int idx = ((bb * H_ + h) * DH_ + d) * S_ + s;
                    Dh[idx] = h0; Dh[idx + S_] = h1;
                    Dl[idx] = l0; Dl[idx + S_] = l1;
                }
            }
        }
    }
}

// ---------------------------------------------------------------------------
// Kernel 2: score GEMMs (fp32 out). z = bh*3 + which.  K = 64.
// ---------------------------------------------------------------------------
__global__ __launch_bounds__(256) void scores_mma()
{
    const int z = blockIdx.z;
    const int bh = z / 3;
    const int which = z - bh * 3;
    const int ho = bh * S_ * DH_;

    const __nv_bfloat16 *Ah, *Al, *Bh, *Bl; float* O;
    if (which == 0)      { Ah = g_qh + ho;  Al = g_ql + ho;  Bh = g_kh + ho;  Bl = g_kl + ho;  O = g_c2c + bh * SS_; }
    else if (which == 1) { Ah = g_qh + ho;  Al = g_ql + ho;  Bh = g_krh + ho; Bl = g_krl + ho; O = g_c2p + bh * SS_; }
    else                 { Ah = g_qrh + ho; Al = g_qrl + ho; Bh = g_kh + ho;  Bl = g_kl + ho;  O = g_p2c + bh * SS_; }

    const int brow = blockIdx.y * 128;
    const int bcol = blockIdx.x * 128;

    float acc[2][8][4] = {};
    gemm_core<8>(Ah + brow * DH_, Al + brow * DH_, DH_,
                 Bh + bcol * DH_, Bl + bcol * DH_, DH_, 2, acc);

    const int lane = threadIdx.x & 31, wid = threadIdx.x >> 5;
    const int wm = wid & 3, wn = wid >> 2;
#pragma unroll
    for (int mt = 0; mt < 2; mt++) {
#pragma unroll
        for (int nt = 0; nt < 8; nt++) {
            const int n = bcol + wn * 64 + nt * 8 + (lane & 3) * 2;
#pragma unroll
            for (int half = 0; half < 2; half++) {
                const int m = brow + wm * 32 + mt * 16 + (lane >> 2) + half * 8;
                *(float2*)(O + m * S_ + n) =
                    make_float2(acc[mt][nt][half * 2], acc[mt][nt][half * 2 + 1]);
            }
        }
    }
}

// ---------------------------------------------------------------------------
// Combine: scores = (c2c + c2p[i, p(i,j)] + p2c[p(i,j), j]) / scale, + mask
// ---------------------------------------------------------------------------
__global__ __launch_bounds__(256) void combine_kernel(const int* __restrict__ mask)
{
    const int bh = blockIdx.z;
    const int b  = bh >> 4;
    const int i0 = blockIdx.y * 32;
    const int j0 = blockIdx.x * 32;
    const int off = bh * SS_;

    __shared__ float c2pS[32][64];
    __shared__ float p2cS[63][32];

    const int base = i0 - j0 - 31 + 512;
    const int tid  = threadIdx.x;

    for (int idx = tid; idx < 32 * 63; idx += 256) {
        const int il = idx / 63;
        const int t  = idx - il * 63;
        const int p  = min(max(base + t, 0), S_ - 1);
        c2pS[il][t] = g_c2p[off + (i0 + il) * S_ + p];
    }
    for (int idx = tid; idx < 63 * 32; idx += 256) {
        const int t  = idx >> 5;
        const int jl = idx & 31;
        const int p  = min(max(base + t, 0), S_ - 1);
        p2cS[t][jl] = g_p2c[off + p * S_ + (j0 + jl)];
    }
    __syncthreads();

    const float invScale = 0.07216878364870323f;  // 1/sqrt(3*64)
    const int jl = tid & 31;
    const int wm = mask[b * S_ + j0 + jl];

#pragma unroll
    for (int pass = 0; pass < 4; pass++) {
        const int il = pass * 8 + (tid >> 5);
        const int t  = il - jl + 31;
        const int idx = off + (i0 + il) * S_ + j0 + jl;
        float sv = (g_c2c[idx] + c2pS[il][t] + p2cS[t][jl]) * invScale;
        if (wm) sv = NEG_INF;
        g_c2c[idx] = sv;
    }
}

// ---------------------------------------------------------------------------
// Softmax: read fp32 scores, write probs as hi/lo bf16.
// ---------------------------------------------------------------------------
__global__ __launch_bounds__(256) void softmax_kernel()
{
    const int rowoff = blockIdx.y * SS_ + blockIdx.x * S_;
    const float* p = g_c2c + rowoff;
    const int tid = threadIdx.x;

    float4 v = *(const float4*)(p + tid * 4);
    float mx = fmaxf(fmaxf(v.x, v.y), fmaxf(v.z, v.w));
#pragma unroll
    for (int o = 16; o > 0; o >>= 1)
        mx = fmaxf(mx, __shfl_xor_sync(0xffffffffu, mx, o));

    __shared__ float smax[8], ssum[8];
    if ((tid & 31) == 0) smax[tid >> 5] = mx;
    __syncthreads();
    mx = fmaxf(fmaxf(fmaxf(smax[0], smax[1]), fmaxf(smax[2], smax[3])),
               fmaxf(fmaxf(smax[4], smax[5]), fmaxf(smax[6], smax[7])));

    v.x = __expf(v.x - mx);
    v.y = __expf(v.y - mx);
    v.z = __expf(v.z - mx);
    v.w = __expf(v.w - mx);
    float s = v.x + v.y + v.z + v.w;
#pragma unroll
    for (int o = 16; o > 0; o >>= 1)
        s += __shfl_xor_sync(0xffffffffu, s, o);
    if ((tid & 31) == 0) ssum[tid >> 5] = s;
    __syncthreads();
    s = ssum[0] + ssum[1] + ssum[2] + ssum[3] +
        ssum[4] + ssum[5] + ssum[6] + ssum[7];

    const float inv = 1.0f / s;
    v.x *= inv; v.y *= inv; v.z *= inv; v.w *= inv;

    __nv_bfloat16 h[4], l[4];
    split1(v.x, h[0], l[0]); split1(v.y, h[1], l[1]);
    split1(v.z, h[2], l[2]); split1(v.w, h[3], l[3]);
    *(uint2*)(g_ph + rowoff + tid * 4) = *(uint2*)h;
    *(uint2*)(g_pl + rowoff + tid * 4) = *(uint2*)l;
}

// ---------------------------------------------------------------------------
// Kernel 3: attn @ V  (probs 1024x1024 @ V 1024x64 per bh) -> ctx hi/lo bf16
// ---------------------------------------------------------------------------
__global__ __launch_bounds__(256) void av_mma()
{
    const int bh = blockIdx.y;
    const int i0 = blockIdx.x * 128;
    const __nv_bfloat16* Ah = g_ph + bh * SS_ + i0 * S_;
    const __nv_bfloat16* Al = g_pl + bh * SS_ + i0 * S_;
    const __nv_bfloat16* Bh = g_vTh + bh * DH_ * S_;
    const __nv_bfloat16* Bl = g_vTl + bh * DH_ * S_;

    float acc[2][4][4] = {};
    gemm_core<4>(Ah, Al, S_, Bh, Bl, S_, 32, acc);

    const int lane = threadIdx.x & 31, wid = threadIdx.x >> 5;
    const int wm = wid & 3, wn = wid >> 2;
    const int b = bh >> 4, h = bh & 15;

#pragma unroll
    for (int mt = 0; mt < 2; mt++) {
#pragma unroll
        for (int nt = 0; nt < 4; nt++) {
            const int d = wn * 32 + nt * 8 + (lane & 3) * 2;
#pragma unroll
            for (int half = 0; half < 2; half++) {
                const int s = i0 + wm * 32 + mt * 16 + (lane >> 2) + half * 8;
                const int idx = (b * S_ + s) * D_ + h * DH_ + d;
                float v0 = acc[mt][nt][half * 2 + 0];
                float v1 = acc[mt][nt][half * 2 + 1];
                __nv_bfloat16 h0, l0, h1, l1;
                split1(v0, h0, l0); split1(v1, h1, l1);
                __nv_bfloat162 ph; ph.x = h0; ph.y = h1;
                __nv_bfloat162 pl; pl.x = l0; pl.y = l1;
                *(__nv_bfloat162*)(g_ctxh + idx) = ph;
                *(__nv_bfloat162*)(g_ctxl + idx) = pl;
            }
        }
    }
}

// ---------------------------------------------------------------------------
// Kernel 4: output projection out = ctx @ Wc^T + bc  (fp32 out)
// ---------------------------------------------------------------------------
__global__ __launch_bounds__(256) void final_mma(
    const float* __restrict__ bc, float* __restrict__ out)
{
    const int brow = blockIdx.y * 128;
    const int bcol = blockIdx.x * 128;

    float acc[2][8][4] = {};
    gemm_core<8>(g_ctxh + brow * D_, g_ctxl + brow * D_, D_,
                 g_Wh[5] + bcol * D_, g_Wl[5] + bcol * D_, D_, 32, acc);

    const int lane = threadIdx.x & 31, wid = threadIdx.x >> 5;
    const int wm = wid & 3, wn = wid >> 2;
#pragma unroll
    for (int mt = 0; mt < 2; mt++) {
#pragma unroll
        for (int nt = 0; nt < 8; nt++) {
            const int n = bcol + wn * 64 + nt * 8 + (lane & 3) * 2;
            const float b0 = __ldg(&bc[n]), b1 = __ldg(&bc[n + 1]);
#pragma unroll
            for (int half = 0; half < 2; half++) {
                const int m = brow + wm * 32 + mt * 16 + (lane >> 2) + half * 8;
                *(float2*)(out + m * D_ + n) =
                    make_float2(acc[mt][nt][half * 2] + b0,
                                acc[mt][nt][half * 2 + 1] + b1);
            }
        }
    }
}

// ---------------------------------------------------------------------------
// Launch
// ---------------------------------------------------------------------------
extern "C" void kernel_launch(void* const* d_in, const int* in_sizes, int n_in,
                              void* d_out, int out_size)
{
    const float* x    = (const float*)d_in[0];
    const float* rel  = (const float*)d_in[1];
    const int*   mask = (const int*)  d_in[2];
    const float* Wq   = (const float*)d_in[3];
    const float* bq   = (const float*)d_in[4];
    const float* Wk   = (const float*)d_in[5];
    const float* bk   = (const float*)d_in[6];
    const float* Wv   = (const float*)d_in[7];
    const float* bv   = (const float*)d_in[8];
    const float* Wqr  = (const float*)d_in[9];
    const float* bqr  = (const float*)d_in[10];
    const float* Wkr  = (const float*)d_in[11];
    const float* bkr  = (const float*)d_in[12];
    const float* Wc   = (const float*)d_in[13];
    const float* bc   = (const float*)d_in[14];
    float* out = (float*)d_out;

    // 0. Split fp32 operands into hi/lo bf16
    const int nXY = ROWS_ * D_ / 4;   // 524288
    const int nW  = D_ * D_ / 4;      // 262144
    convert_kernel<<<nXY / 256, 256>>>(x,   0, nXY);
    convert_kernel<<<nXY / 256, 256>>>(rel, 1, nXY);
    convert_kernel<<<nW  / 256, 256>>>(Wq,  2, nW);
    convert_kernel<<<nW  / 256, 256>>>(Wk,  3, nW);
    convert_kernel<<<nW  / 256, 256>>>(Wv,  4, nW);
    convert_kernel<<<nW  / 256, 256>>>(Wqr, 5, nW);
    convert_kernel<<<nW  / 256, 256>>>(Wkr, 6, nW);
    convert_kernel<<<nW  / 256, 256>>>(Wc,  7, nW);

    // 1. Projections (HMMA, z-fused)
    proj_mma<<<dim3(D_ / 128, ROWS_ / 128, 5), 256>>>(bq, bk, bv, bqr, bkr);

    // 2. Score GEMMs
    scores_mma<<<dim3(S_ / 128, S_ / 128, BH_ * 3), 256>>>();

    // 3. Banded gather + sum + scale + mask
    combine_kernel<<<dim3(S_ / 32, S_ / 32, BH_), 256>>>(mask);

    // 4. Softmax -> probs hi/lo bf16
    softmax_kernel<<<dim3(S_, BH_), 256>>>();

    // 5. attn @ V -> ctx hi/lo bf16
    av_mma<<<dim3(S_ / 128, BH_), 256>>>();

    // 6. Output projection
    final_mma<<<dim3(D_ / 128, ROWS_ / 128), 256>>>(bc, out);
}

// round 5
// speedup vs baseline: 2.5263x; 1.1698x over previous
#include <cuda_runtime.h>
#include <cuda_bf16.h>

// Problem constants
#define B_    2
#define S_    1024
#define D_    1024
#define H_    16
#define DH_   64
#define BH_   (B_*H_)      // 32
#define ROWS_ (B_*S_)      // 2048
#define SS_   (S_*S_)      // 1048576

#define NEG_INF __int_as_float(0xff800000)

// ---------------------------------------------------------------------------
// Device-global scratch (allocation-free rule). bf16 operands split hi/lo.
// ---------------------------------------------------------------------------
__device__ __align__(16) __nv_bfloat16 g_xh [ROWS_*D_], g_xl [ROWS_*D_];
__device__ __align__(16) __nv_bfloat16 g_relh[ROWS_*D_], g_rell[ROWS_*D_];
__device__ __align__(16) __nv_bfloat16 g_Wh[6][D_*D_],  g_Wl[6][D_*D_]; // q,k,v,qr,kr,c

__device__ __align__(16) __nv_bfloat16 g_qh [BH_*S_*DH_], g_ql [BH_*S_*DH_];
__device__ __align__(16) __nv_bfloat16 g_kh [BH_*S_*DH_], g_kl [BH_*S_*DH_];
__device__ __align__(16) __nv_bfloat16 g_qrh[BH_*S_*DH_], g_qrl[BH_*S_*DH_];
__device__ __align__(16) __nv_bfloat16 g_krh[BH_*S_*DH_], g_krl[BH_*S_*DH_];
__device__ __align__(16) __nv_bfloat16 g_vTh[BH_*DH_*S_], g_vTl[BH_*DH_*S_]; // [bh][d][s]

__device__ __align__(16) float g_c2c[BH_*SS_];
__device__ __align__(16) float g_c2p[BH_*SS_];
__device__ __align__(16) float g_p2c[BH_*SS_];

__device__ __align__(16) __nv_bfloat16 g_ph[BH_*SS_], g_pl[BH_*SS_];     // probs
__device__ __align__(16) __nv_bfloat16 g_ctxh[ROWS_*D_], g_ctxl[ROWS_*D_];

// ---------------------------------------------------------------------------
// Helpers
// ---------------------------------------------------------------------------
__device__ __forceinline__ unsigned smem_u32(const void* p) {
    unsigned a;
    asm("{ .reg .u64 t; cvta.to.shared.u64 t, %1; cvt.u32.u64 %0, t; }"
        : "=r"(a) : "l"(p));
    return a;
}

__device__ __forceinline__ void ldsm4(unsigned r[4], unsigned a) {
    asm volatile("ldmatrix.sync.aligned.m8n8.x4.shared.b16 {%0,%1,%2,%3}, [%4];"
        : "=r"(r[0]), "=r"(r[1]), "=r"(r[2]), "=r"(r[3]) : "r"(a));
}

__device__ __forceinline__ void mma_bf16(float c[4], const unsigned a[4],
                                         unsigned b0, unsigned b1) {
    asm volatile(
        "mma.sync.aligned.m16n8k16.row.col.f32.bf16.bf16.f32 "
        "{%0,%1,%2,%3}, {%4,%5,%6,%7}, {%8,%9}, {%0,%1,%2,%3};"
        : "+f"(c[0]), "+f"(c[1]), "+f"(c[2]), "+f"(c[3])
        : "r"(a[0]), "r"(a[1]), "r"(a[2]), "r"(a[3]), "r"(b0), "r"(b1));
}

__device__ __forceinline__ void split1(float a, __nv_bfloat16& h, __nv_bfloat16& l) {
    h = __float2bfloat16(a);
    l = __float2bfloat16(a - __bfloat162float(h));
}

__device__ __forceinline__ void cp16(unsigned s, const void* g) {
    asm volatile("cp.async.cg.shared.global [%0], [%1], 16;" :: "r"(s), "l"(g));
}
#define CP_COMMIT() asm volatile("cp.async.commit_group;" ::: "memory")
#define CP_WAIT0()  asm volatile("cp.async.wait_group 0;" ::: "memory")
#define CP_WAIT1()  asm volatile("cp.async.wait_group 1;" ::: "memory")

// ---------------------------------------------------------------------------
// Operand conversion: fp32 -> hi/lo bf16, all 8 tensors in one launch.
// x: [0, 524288) f4 | rel: [524288, 1048576) | W0..W5: 262144 f4 each after.
// ---------------------------------------------------------------------------
__global__ __launch_bounds__(256) void convert_all(
    const float* __restrict__ x,  const float* __restrict__ rel,
    const float* __restrict__ W0, const float* __restrict__ W1,
    const float* __restrict__ W2, const float* __restrict__ W3,
    const float* __restrict__ W4, const float* __restrict__ W5)
{
    const int i = blockIdx.x * 256 + threadIdx.x;   // grid covers 2621440
    const float* src; __nv_bfloat16 *Dh, *Dl; int off;
    if (i < 1048576) {
        if (i < 524288) { src = x;   Dh = g_xh;   Dl = g_xl;   off = i; }
        else            { src = rel; Dh = g_relh; Dl = g_rell; off = i - 524288; }
    } else {
        const int w = (i - 1048576) >> 18;
        off = (i - 1048576) & 262143;
        switch (w) {
            case 0:  src = W0; break; case 1: src = W1; break;
            case 2:  src = W2; break; case 3: src = W3; break;
            case 4:  src = W4; break; default: src = W5; break;
        }
        Dh = g_Wh[w]; Dl = g_Wl[w];
    }
    float4 v = ((const float4*)src)[off];
    __nv_bfloat16 h[4], l[4];
    split1(v.x, h[0], l[0]); split1(v.y, h[1], l[1]);
    split1(v.z, h[2], l[2]); split1(v.w, h[3], l[3]);
    *(uint2*)(Dh + off * 4) = *(uint2*)h;
    *(uint2*)(Dl + off * 4) = *(uint2*)l;
}

// ---------------------------------------------------------------------------
// HMMA GEMM core, cp.async double-buffered.
// Block = 128 x (NT*16). 256 threads = 8 warps (4m x 2n).
// K-chunk = 32. A,B K-major bf16 hi/lo. bf16x3: Ah*Bh + Ah*Bl + Al*Bh.
// SMEM pitch 40 bf16 (80B): conflict-free staging + ldmatrix.
// Dynamic SMEM, 2 stages: stage = {Ah, Al, Bh, Bl}.
// ---------------------------------------------------------------------------
template<int NT>
__device__ __forceinline__ void gemm_core(
    const __nv_bfloat16* __restrict__ Ah, const __nv_bfloat16* __restrict__ Al, int lda,
    const __nv_bfloat16* __restrict__ Bh, const __nv_bfloat16* __restrict__ Bl, int ldb,
    int ktiles, float acc[2][NT][4])
{
    extern __shared__ __align__(16) __nv_bfloat16 dyn[];
    constexpr int ABYTES = 128 * 40 * 2;        // 10240
    constexpr int BBYTES = NT * 16 * 40 * 2;
    constexpr int STGB   = 2 * ABYTES + 2 * BBYTES;

    const int tid  = threadIdx.x;
    const int lane = tid & 31;
    const int wid  = tid >> 5;
    const int wm   = wid & 3;
    const int wn   = wid >> 2;
    const unsigned uB = smem_u32(dyn);

    // ldmatrix line address components (bytes, relative to array base)
    const unsigned aoff = (unsigned)((wm * 32 + (lane & 15)) * 80 + ((lane >> 4) << 4));
    const unsigned boff = (unsigned)((wn * (NT * 8) + (lane & 7) + ((lane >> 4) << 3)) * 80
                                     + (((lane >> 3) & 1) << 4));

    auto issue = [&](int st, int kt) {
        const int kb = kt * 32;
        const unsigned sbase = uB + st * STGB;
#pragma unroll
        for (int s = 0; s < 2; s++) {                 // A: 512 chunks
            int ch = s * 256 + tid;
            int r = ch >> 2, ks = ch & 3;
            unsigned o = (unsigned)(r * 80 + ks * 16);
            const __nv_bfloat16* gp = Ah + r * lda + kb + ks * 8;
            const __nv_bfloat16* gq = Al + r * lda + kb + ks * 8;
            cp16(sbase + o, gp);
            cp16(sbase + ABYTES + o, gq);
        }
#pragma unroll
        for (int s = 0; s < NT / 4; s++) {            // B: NT*64 chunks
            int ch = s * 256 + tid;
            int r = ch >> 2, ks = ch & 3;
            unsigned o = (unsigned)(r * 80 + ks * 16);
            const __nv_bfloat16* gp = Bh + r * ldb + kb + ks * 8;
            const __nv_bfloat16* gq = Bl + r * ldb + kb + ks * 8;
            cp16(sbase + 2 * ABYTES + o, gp);
            cp16(sbase + 2 * ABYTES + BBYTES + o, gq);
        }
        CP_COMMIT();
    };

    issue(0, 0);

    for (int kt = 0; kt < ktiles; kt++) {
        const int st = kt & 1;
        if (kt + 1 < ktiles) { issue(st ^ 1, kt + 1); CP_WAIT1(); }
        else                 { CP_WAIT0(); }
        __syncthreads();

        const unsigned sbase = uB + st * STGB;
        const unsigned uAh = sbase, uAl = sbase + ABYTES;
        const unsigned uBh = sbase + 2 * ABYTES, uBl = uBh + BBYTES;

#pragma unroll
        for (int ks = 0; ks < 2; ks++) {
            unsigned ah[2][4], al[2][4];
#pragma unroll
            for (int mt = 0; mt < 2; mt++) {
                unsigned o = aoff + mt * 16 * 80 + ks * 32;
                ldsm4(ah[mt], uAh + o);
                ldsm4(al[mt], uAl + o);
            }
#pragma unroll
            for (int np = 0; np < NT / 2; np++) {
                unsigned o = boff + np * 16 * 80 + ks * 32;
                unsigned bh[4], bl[4];
                ldsm4(bh, uBh + o);
                ldsm4(bl, uBl + o);
#pragma unroll
                for (int mt = 0; mt < 2; mt++) {
#pragma unroll
                    for (int sub = 0; sub < 2; sub++) {
                        float* c = acc[mt][np * 2 + sub];
                        mma_bf16(c, ah[mt], bh[sub * 2], bh[sub * 2 + 1]);
                        mma_bf16(c, ah[mt], bl[sub * 2], bl[sub * 2 + 1]);
                        mma_bf16(c, al[mt], bh[sub * 2], bh[sub * 2 + 1]);
                    }
                }
            }
        }
        __syncthreads();
    }
}

#define SMEM_NT8 (2 * (2 * 128 * 40 * 2 + 2 * 8 * 16 * 40 * 2))   // 81920
#define SMEM_NT4 (2 * (2 * 128 * 40 * 2 + 2 * 4 * 16 * 40 * 2))   // 61440

// ---------------------------------------------------------------------------
// Kernel 1: projections. z: 0=Q 1=K 2=V 3=QR 4=KR.  out head-major hi/lo bf16.
// ---------------------------------------------------------------------------
__global__ __launch_bounds__(256) void proj_mma(
    const float* __restrict__ bq, const float* __restrict__ bk,
    const float* __restrict__ bv, const float* __restrict__ bqr,
    const float* __restrict__ bkr)
{
    const int z = blockIdx.z;
    const __nv_bfloat16 *Ah, *Al;
    if (z < 3) { Ah = g_xh; Al = g_xl; } else { Ah = g_relh; Al = g_rell; }
    const __nv_bfloat16* Bh = g_Wh[z];
    const __nv_bfloat16* Bl = g_Wl[z];

    __nv_bfloat16 *Dh, *Dl; const float* bias;
    switch (z) {
        case 0:  Dh = g_qh;  Dl = g_ql;  bias = bq;  break;
        case 1:  Dh = g_kh;  Dl = g_kl;  bias = bk;  break;
        case 2:  Dh = g_vTh; Dl = g_vTl; bias = bv;  break;
        case 3:  Dh = g_qrh; Dl = g_qrl; bias = bqr; break;
        default: Dh = g_krh; Dl = g_krl; bias = bkr; break;
    }

    const int brow = blockIdx.y * 128;
    const int bcol = blockIdx.x * 128;

    float acc[2][8][4] = {};
    gemm_core<8>(Ah + brow * D_, Al + brow * D_, D_,
                 Bh + bcol * D_, Bl + bcol * D_, D_, 32, acc);

    const int lane = threadIdx.x & 31, wid = threadIdx.x >> 5;
    const int wm = wid & 3, wn = wid >> 2;
    const bool vtrans = (z == 2);

#pragma unroll
    for (int mt = 0; mt < 2; mt++) {
#pragma unroll
        for (int nt = 0; nt < 8; nt++) {
            const int n = bcol + wn * 64 + nt * 8 + (lane & 3) * 2;
            const int h = n >> 6, d = n & 63;
            const float b0 = __ldg(&bias[n]), b1 = __ldg(&bias[n + 1]);
#pragma unroll
            for (int half = 0; half < 2; half++) {
                const int m = brow + wm * 32 + mt * 16 + (lane >> 2) + half * 8;
                const int bb = m >> 10, s = m & (S_ - 1);
                float v0 = acc[mt][nt][half * 2 + 0] + b0;
                float v1 = acc[mt][nt][half * 2 + 1] + b1;
                __nv_bfloat16 h0, l0, h1, l1;
                split1(v0, h0, l0); split1(v1, h1, l1);
                if (!vtrans) {
                    const int idx = ((bb * H_ + h) * S_ + s) * DH_ + d;
                    __nv_bfloat162 ph; ph.x = h0; ph.y = h1;
                    __nv_bfloat162 pl; pl.x = l0; pl.y = l1;
                    *(__nv_bfloat162*)(Dh + idx) = ph;
                    *(__nv_bfloat162*)(Dl + idx) = pl;
                } else {
                    const int idx = ((bb * H_ + h) * DH_ + d) * S_ + s;
                    Dh[idx] = h0; Dh[idx + S_] = h1;
                    Dl[idx] = l0; Dl[idx + S_] = l1;
                }
            }
        }
    }
}

// ---------------------------------------------------------------------------
// Kernel 2: score GEMMs (fp32 out). z = bh*3 + which.  K = 64.
// ---------------------------------------------------------------------------
__global__ __launch_bounds__(256) void scores_mma()
{
    const int z = blockIdx.z;
    const int bh = z / 3;
    const int which = z - bh * 3;
    const int ho = bh * S_ * DH_;

    const __nv_bfloat16 *Ah, *Al, *Bh, *Bl; float* O;
    if (which == 0)      { Ah = g_qh + ho;  Al = g_ql + ho;  Bh = g_kh + ho;  Bl = g_kl + ho;  O = g_c2c + bh * SS_; }
    else if (which == 1) { Ah = g_qh + ho;  Al = g_ql + ho;  Bh = g_krh + ho; Bl = g_krl + ho; O = g_c2p + bh * SS_; }
    else                 { Ah = g_qrh + ho; Al = g_qrl + ho; Bh = g_kh + ho;  Bl = g_kl + ho;  O = g_p2c + bh * SS_; }

    const int brow = blockIdx.y * 128;
    const int bcol = blockIdx.x * 128;

    float acc[2][8][4] = {};
    gemm_core<8>(Ah + brow * DH_, Al + brow * DH_, DH_,
                 Bh + bcol * DH_, Bl + bcol * DH_, DH_, 2, acc);

    const int lane = threadIdx.x & 31, wid = threadIdx.x >> 5;
    const int wm = wid & 3, wn = wid >> 2;
#pragma unroll
    for (int mt = 0; mt < 2; mt++) {
#pragma unroll
        for (int nt = 0; nt < 8; nt++) {
            const int n = bcol + wn * 64 + nt * 8 + (lane & 3) * 2;
#pragma unroll
            for (int half = 0; half < 2; half++) {
                const int m = brow + wm * 32 + mt * 16 + (lane >> 2) + half * 8;
                *(float2*)(O + m * S_ + n) =
                    make_float2(acc[mt][nt][half * 2], acc[mt][nt][half * 2 + 1]);
            }
        }
    }
}

// ---------------------------------------------------------------------------
// Combine: scores = (c2c + c2p[i, p(i,j)] + p2c[p(i,j), j]) / scale, + mask
// ---------------------------------------------------------------------------
__global__ __launch_bounds__(256) void combine_kernel(const int* __restrict__ mask)
{
    const int bh = blockIdx.z;
    const int b  = bh >> 4;
    const int i0 = blockIdx.y * 32;
    const int j0 = blockIdx.x * 32;
    const int off = bh * SS_;

    __shared__ float c2pS[32][64];
    __shared__ float p2cS[63][32];

    const int base = i0 - j0 - 31 + 512;
    const int tid  = threadIdx.x;

    for (int idx = tid; idx < 32 * 63; idx += 256) {
        const int il = idx / 63;
        const int t  = idx - il * 63;
        const int p  = min(max(base + t, 0), S_ - 1);
        c2pS[il][t] = g_c2p[off + (i0 + il) * S_ + p];
    }
    for (int idx = tid; idx < 63 * 32; idx += 256) {
        const int t  = idx >> 5;
        const int jl = idx & 31;
        const int p  = min(max(base + t, 0), S_ - 1);
        p2cS[t][jl] = g_p2c[off + p * S_ + (j0 + jl)];
    }
    __syncthreads();

    const float invScale = 0.07216878364870323f;  // 1/sqrt(3*64)
    const int jl = tid & 31;
    const int wm = mask[b * S_ + j0 + jl];

#pragma unroll
    for (int pass = 0; pass < 4; pass++) {
        const int il = pass * 8 + (tid >> 5);
        const int t  = il - jl + 31;
        const int idx = off + (i0 + il) * S_ + j0 + jl;
        float sv = (g_c2c[idx] + c2pS[il][t] + p2cS[t][jl]) * invScale;
        if (wm) sv = NEG_INF;
        g_c2c[idx] = sv;
    }
}

// ---------------------------------------------------------------------------
// Softmax: read fp32 scores, write probs as hi/lo bf16.
// ---------------------------------------------------------------------------
__global__ __launch_bounds__(256) void softmax_kernel()
{
    const int rowoff = blockIdx.y * SS_ + blockIdx.x * S_;
    const float* p = g_c2c + rowoff;
    const int tid = threadIdx.x;

    float4 v = *(const float4*)(p + tid * 4);
    float mx = fmaxf(fmaxf(v.x, v.y), fmaxf(v.z, v.w));
#pragma unroll
    for (int o = 16; o > 0; o >>= 1)
        mx = fmaxf(mx, __shfl_xor_sync(0xffffffffu, mx, o));

    __shared__ float smax[8], ssum[8];
    if ((tid & 31) == 0) smax[tid >> 5] = mx;
    __syncthreads();
    mx = fmaxf(fmaxf(fmaxf(smax[0], smax[1]), fmaxf(smax[2], smax[3])),
               fmaxf(fmaxf(smax[4], smax[5]), fmaxf(smax[6], smax[7])));

    v.x = __expf(v.x - mx);
    v.y = __expf(v.y - mx);
    v.z = __expf(v.z - mx);
    v.w = __expf(v.w - mx);
    float s = v.x + v.y + v.z + v.w;
#pragma unroll
    for (int o = 16; o > 0; o >>= 1)
        s += __shfl_xor_sync(0xffffffffu, s, o);
    if ((tid & 31) == 0) ssum[tid >> 5] = s;
    __syncthreads();
    s = ssum[0] + ssum[1] + ssum[2] + ssum[3] +
        ssum[4] + ssum[5] + ssum[6] + ssum[7];

    const float inv = 1.0f / s;
    v.x *= inv; v.y *= inv; v.z *= inv; v.w *= inv;

    __nv_bfloat16 h[4], l[4];
    split1(v.x, h[0], l[0]); split1(v.y, h[1], l[1]);
    split1(v.z, h[2], l[2]); split1(v.w, h[3], l[3]);
    *(uint2*)(g_ph + rowoff + tid * 4) = *(uint2*)h;
    *(uint2*)(g_pl + rowoff + tid * 4) = *(uint2*)l;
}

// ---------------------------------------------------------------------------
// Kernel 3: attn @ V  (probs 1024x1024 @ V 1024x64 per bh) -> ctx hi/lo bf16
// ---------------------------------------------------------------------------
__global__ __launch_bounds__(256) void av_mma()
{
    const int bh = blockIdx.y;
    const int i0 = blockIdx.x * 128;
    const __nv_bfloat16* Ah = g_ph + bh * SS_ + i0 * S_;
    const __nv_bfloat16* Al = g_pl + bh * SS_ + i0 * S_;
    const __nv_bfloat16* Bh = g_vTh + bh * DH_ * S_;
    const __nv_bfloat16* Bl = g_vTl + bh * DH_ * S_;

    float acc[2][4][4] = {};
    gemm_core<4>(Ah, Al, S_, Bh, Bl, S_, 32, acc);

    const int lane = threadIdx.x & 31, wid = threadIdx.x >> 5;
    const int wm = wid & 3, wn = wid >> 2;
    const int b = bh >> 4, h = bh & 15;

#pragma unroll
    for (int mt = 0; mt < 2; mt++) {
#pragma unroll
        for (int nt = 0; nt < 4; nt++) {
            const int d = wn * 32 + nt * 8 + (lane & 3) * 2;
#pragma unroll
            for (int half = 0; half < 2; half++) {
                const int s = i0 + wm * 32 + mt * 16 + (lane >> 2) + half * 8;
                const int idx = (b * S_ + s) * D_ + h * DH_ + d;
                float v0 = acc[mt][nt][half * 2 + 0];
                float v1 = acc[mt][nt][half * 2 + 1];
                __nv_bfloat16 h0, l0, h1, l1;
                split1(v0, h0, l0); split1(v1, h1, l1);
                __nv_bfloat162 ph; ph.x = h0; ph.y = h1;
                __nv_bfloat162 pl; pl.x = l0; pl.y = l1;
                *(__nv_bfloat162*)(g_ctxh + idx) = ph;
                *(__nv_bfloat162*)(g_ctxl + idx) = pl;
            }
        }
    }
}

// ---------------------------------------------------------------------------
// Kernel 4: output projection out = ctx @ Wc^T + bc  (fp32 out)
// ---------------------------------------------------------------------------
__global__ __launch_bounds__(256) void final_mma(
    const float* __restrict__ bc, float* __restrict__ out)
{
    const int brow = blockIdx.y * 128;
    const int bcol = blockIdx.x * 128;

    float acc[2][8][4] = {};
    gemm_core<8>(g_ctxh + brow * D_, g_ctxl + brow * D_, D_,
                 g_Wh[5] + bcol * D_, g_Wl[5] + bcol * D_, D_, 32, acc);

    const int lane = threadIdx.x & 31, wid = threadIdx.x >> 5;
    const int wm = wid & 3, wn = wid >> 2;
#pragma unroll
    for (int mt = 0; mt < 2; mt++) {
#pragma unroll
        for (int nt = 0; nt < 8; nt++) {
            const int n = bcol + wn * 64 + nt * 8 + (lane & 3) * 2;
            const float b0 = __ldg(&bc[n]), b1 = __ldg(&bc[n + 1]);
#pragma unroll
            for (int half = 0; half < 2; half++) {
                const int m = brow + wm * 32 + mt * 16 + (lane >> 2) + half * 8;
                *(float2*)(out + m * D_ + n) =
                    make_float2(acc[mt][nt][half * 2] + b0,
                                acc[mt][nt][half * 2 + 1] + b1);
            }
        }
    }
}

// ---------------------------------------------------------------------------
// Launch
// ---------------------------------------------------------------------------
extern "C" void kernel_launch(void* const* d_in, const int* in_sizes, int n_in,
                              void* d_out, int out_size)
{
    const float* x    = (const float*)d_in[0];
    const float* rel  = (const float*)d_in[1];
    const int*   mask = (const int*)  d_in[2];
    const float* Wq   = (const float*)d_in[3];
    const float* bq   = (const float*)d_in[4];
    const float* Wk   = (const float*)d_in[5];
    const float* bk   = (const float*)d_in[6];
    const float* Wv   = (const float*)d_in[7];
    const float* bv   = (const float*)d_in[8];
    const float* Wqr  = (const float*)d_in[9];
    const float* bqr  = (const float*)d_in[10];
    const float* Wkr  = (const float*)d_in[11];
    const float* bkr  = (const float*)d_in[12];
    const float* Wc   = (const float*)d_in[13];
    const float* bc   = (const float*)d_in[14];
    float* out = (float*)d_out;

    static int attr_done = 0;
    if (!attr_done) {
        cudaFuncSetAttribute(proj_mma,   cudaFuncAttributeMaxDynamicSharedMemorySize, SMEM_NT8);
        cudaFuncSetAttribute(scores_mma, cudaFuncAttributeMaxDynamicSharedMemorySize, SMEM_NT8);
        cudaFuncSetAttribute(av_mma,     cudaFuncAttributeMaxDynamicSharedMemorySize, SMEM_NT4);
        cudaFuncSetAttribute(final_mma,  cudaFuncAttributeMaxDynamicSharedMemorySize, SMEM_NT8);
        attr_done = 1;
    }

    // 0. Split fp32 operands into hi/lo bf16 (single launch)
    convert_all<<<2621440 / 256, 256>>>(x, rel, Wq, Wk, Wv, Wqr, Wkr, Wc);

    // 1. Projections (HMMA, z-fused)
    proj_mma<<<dim3(D_ / 128, ROWS_ / 128, 5), 256, SMEM_NT8>>>(bq, bk, bv, bqr, bkr);

    // 2. Score GEMMs
    scores_mma<<<dim3(S_ / 128, S_ / 128, BH_ * 3), 256, SMEM_NT8>>>();

    // 3. Banded gather + sum + scale + mask
    combine_kernel<<<dim3(S_ / 32, S_ / 32, BH_), 256>>>(mask);

    // 4. Softmax -> probs hi/lo bf16
    softmax_kernel<<<dim3(S_, BH_), 256>>>();

    // 5. attn @ V -> ctx hi/lo bf16
    av_mma<<<dim3(S_ / 128, BH_), 256, SMEM_NT4>>>();

    // 6. Output projection
    final_mma<<<dim3(D_ / 128, ROWS_ / 128), 256, SMEM_NT8>>>(bc, out);
}

// round 8
// speedup vs baseline: 3.1019x; 1.2278x over previous
#include <cuda_runtime.h>
#include <cuda_bf16.h>

// Problem constants
#define B_    2
#define S_    1024
#define D_    1024
#define H_    16
#define DH_   64
#define BH_   (B_*H_)      // 32
#define ROWS_ (B_*S_)      // 2048
#define SS_   (S_*S_)      // 1048576

#define NEG_INF __int_as_float(0xff800000)

// ---------------------------------------------------------------------------
// Device-global scratch (allocation-free rule). bf16 operands split hi/lo.
// ---------------------------------------------------------------------------
__device__ __align__(16) __nv_bfloat16 g_xh [ROWS_*D_], g_xl [ROWS_*D_];
__device__ __align__(16) __nv_bfloat16 g_relh[ROWS_*D_], g_rell[ROWS_*D_];
__device__ __align__(16) __nv_bfloat16 g_Wh[6][D_*D_],  g_Wl[6][D_*D_]; // q,k,v,qr,kr,c

__device__ __align__(16) __nv_bfloat16 g_qh [BH_*S_*DH_], g_ql [BH_*S_*DH_];
__device__ __align__(16) __nv_bfloat16 g_kh [BH_*S_*DH_], g_kl [BH_*S_*DH_];
__device__ __align__(16) __nv_bfloat16 g_qrh[BH_*S_*DH_], g_qrl[BH_*S_*DH_];
__device__ __align__(16) __nv_bfloat16 g_krh[BH_*S_*DH_], g_krl[BH_*S_*DH_];
__device__ __align__(16) __nv_bfloat16 g_vTh[BH_*DH_*S_], g_vTl[BH_*DH_*S_]; // [bh][d][s]

__device__ __align__(16) float g_c2c[BH_*SS_];
__device__ __align__(16) float g_c2p[BH_*SS_];
__device__ __align__(16) float g_p2c[BH_*SS_];

__device__ __align__(16) __nv_bfloat16 g_ph[BH_*SS_], g_pl[BH_*SS_];     // probs
__device__ __align__(16) __nv_bfloat16 g_ctxh[ROWS_*D_], g_ctxl[ROWS_*D_];

// ---------------------------------------------------------------------------
// Helpers
// ---------------------------------------------------------------------------
__device__ __forceinline__ unsigned smem_u32(const void* p) {
    unsigned a;
    asm("{ .reg .u64 t; cvta.to.shared.u64 t, %1; cvt.u32.u64 %0, t; }"
        : "=r"(a) : "l"(p));
    return a;
}

__device__ __forceinline__ void ldsm4(unsigned r[4], unsigned a) {
    asm volatile("ldmatrix.sync.aligned.m8n8.x4.shared.b16 {%0,%1,%2,%3}, [%4];"
        : "=r"(r[0]), "=r"(r[1]), "=r"(r[2]), "=r"(r[3]) : "r"(a));
}

__device__ __forceinline__ void mma_bf16(float c[4], const unsigned a[4],
                                         unsigned b0, unsigned b1) {
    asm volatile(
        "mma.sync.aligned.m16n8k16.row.col.f32.bf16.bf16.f32 "
        "{%0,%1,%2,%3}, {%4,%5,%6,%7}, {%8,%9}, {%0,%1,%2,%3};"
        : "+f"(c[0]), "+f"(c[1]), "+f"(c[2]), "+f"(c[3])
        : "r"(a[0]), "r"(a[1]), "r"(a[2]), "r"(a[3]), "r"(b0), "r"(b1));
}

__device__ __forceinline__ void split1(float a, __nv_bfloat16& h, __nv_bfloat16& l) {
    h = __float2bfloat16(a);
    l = __float2bfloat16(a - __bfloat162float(h));
}

__device__ __forceinline__ void cp16(unsigned s, const void* g) {
    asm volatile("cp.async.cg.shared.global [%0], [%1], 16;" :: "r"(s), "l"(g));
}
#define CP_COMMIT() asm volatile("cp.async.commit_group;" ::: "memory")
#define CP_WAIT0()  asm volatile("cp.async.wait_group 0;" ::: "memory")
#define CP_WAIT1()  asm volatile("cp.async.wait_group 1;" ::: "memory")

// ---------------------------------------------------------------------------
// Operand conversion: fp32 -> hi/lo bf16, all 8 tensors in one launch.
// ---------------------------------------------------------------------------
__global__ __launch_bounds__(256) void convert_all(
    const float* __restrict__ x,  const float* __restrict__ rel,
    const float* __restrict__ W0, const float* __restrict__ W1,
    const float* __restrict__ W2, const float* __restrict__ W3,
    const float* __restrict__ W4, const float* __restrict__ W5)
{
    const int i = blockIdx.x * 256 + threadIdx.x;   // grid covers 2621440
    const float* src; __nv_bfloat16 *Dh, *Dl; int off;
    if (i < 1048576) {
        if (i < 524288) { src = x;   Dh = g_xh;   Dl = g_xl;   off = i; }
        else            { src = rel; Dh = g_relh; Dl = g_rell; off = i - 524288; }
    } else {
        const int w = (i - 1048576) >> 18;
        off = (i - 1048576) & 262143;
        switch (w) {
            case 0:  src = W0; break; case 1: src = W1; break;
            case 2:  src = W2; break; case 3: src = W3; break;
            case 4:  src = W4; break; default: src = W5; break;
        }
        Dh = g_Wh[w]; Dl = g_Wl[w];
    }
    float4 v = ((const float4*)src)[off];
    __nv_bfloat16 h[4], l[4];
    split1(v.x, h[0], l[0]); split1(v.y, h[1], l[1]);
    split1(v.z, h[2], l[2]); split1(v.w, h[3], l[3]);
    *(uint2*)(Dh + off * 4) = *(uint2*)h;
    *(uint2*)(Dl + off * 4) = *(uint2*)l;
}

// ---------------------------------------------------------------------------
// HMMA GEMM core, cp.async double-buffered.
// ---------------------------------------------------------------------------
template<int NT>
__device__ __forceinline__ void gemm_core(
    const __nv_bfloat16* __restrict__ Ah, const __nv_bfloat16* __restrict__ Al, int lda,
    const __nv_bfloat16* __restrict__ Bh, const __nv_bfloat16* __restrict__ Bl, int ldb,
    int ktiles, float acc[2][NT][4])
{
    extern __shared__ __align__(16) __nv_bfloat16 dyn[];
    constexpr int ABYTES = 128 * 40 * 2;        // 10240
    constexpr int BBYTES = NT * 16 * 40 * 2;
    constexpr int STGB   = 2 * ABYTES + 2 * BBYTES;

    const int tid  = threadIdx.x;
    const int lane = tid & 31;
    const int wid  = tid >> 5;
    const int wm   = wid & 3;
    const int wn   = wid >> 2;
    const unsigned uB = smem_u32(dyn);

    const unsigned aoff = (unsigned)((wm * 32 + (lane & 15)) * 80 + ((lane >> 4) << 4));
    const unsigned boff = (unsigned)((wn * (NT * 8) + (lane & 7) + ((lane >> 4) << 3)) * 80
                                     + (((lane >> 3) & 1) << 4));

    auto issue = [&](int st, int kt) {
        const int kb = kt * 32;
        const unsigned sbase = uB + st * STGB;
#pragma unroll
        for (int s = 0; s < 2; s++) {                 // A: 512 chunks
            int ch = s * 256 + tid;
            int r = ch >> 2, ks = ch & 3;
            unsigned o = (unsigned)(r * 80 + ks * 16);
            cp16(sbase + o, Ah + r * lda + kb + ks * 8);
            cp16(sbase + ABYTES + o, Al + r * lda + kb + ks * 8);
        }
#pragma unroll
        for (int s = 0; s < NT / 4; s++) {            // B: NT*64 chunks
            int ch = s * 256 + tid;
            int r = ch >> 2, ks = ch & 3;
            unsigned o = (unsigned)(r * 80 + ks * 16);
            cp16(sbase + 2 * ABYTES + o, Bh + r * ldb + kb + ks * 8);
            cp16(sbase + 2 * ABYTES + BBYTES + o, Bl + r * ldb + kb + ks * 8);
        }
        CP_COMMIT();
    };

    issue(0, 0);

    for (int kt = 0; kt < ktiles; kt++) {
        const int st = kt & 1;
        if (kt + 1 < ktiles) { issue(st ^ 1, kt + 1); CP_WAIT1(); }
        else                 { CP_WAIT0(); }
        __syncthreads();

        const unsigned sbase = uB + st * STGB;
        const unsigned uAh = sbase, uAl = sbase + ABYTES;
        const unsigned uBh = sbase + 2 * ABYTES, uBl = uBh + BBYTES;

#pragma unroll
        for (int ks = 0; ks < 2; ks++) {
            unsigned ah[2][4], al[2][4];
#pragma unroll
            for (int mt = 0; mt < 2; mt++) {
                unsigned o = aoff + mt * 16 * 80 + ks * 32;
                ldsm4(ah[mt], uAh + o);
                ldsm4(al[mt], uAl + o);
            }
#pragma unroll
            for (int np = 0; np < NT / 2; np++) {
                unsigned o = boff + np * 16 * 80 + ks * 32;
                unsigned bh[4], bl[4];
                ldsm4(bh, uBh + o);
                ldsm4(bl, uBl + o);
#pragma unroll
                for (int mt = 0; mt < 2; mt++) {
#pragma unroll
                    for (int sub = 0; sub < 2; sub++) {
                        float* c = acc[mt][np * 2 + sub];
                        mma_bf16(c, ah[mt], bh[sub * 2], bh[sub * 2 + 1]);
                        mma_bf16(c, ah[mt], bl[sub * 2], bl[sub * 2 + 1]);
                        mma_bf16(c, al[mt], bh[sub * 2], bh[sub * 2 + 1]);
                    }
                }
            }
        }
        __syncthreads();
    }
}

#define SMEM_NT8 (2 * (2 * 128 * 40 * 2 + 2 * 8 * 16 * 40 * 2))   // 81920
#define SMEM_NT4 (2 * (2 * 128 * 40 * 2 + 2 * 4 * 16 * 40 * 2))   // 61440

// ---------------------------------------------------------------------------
// Kernel 1: projections. z: 0=Q 1=K 2=V 3=QR 4=KR.  out head-major hi/lo bf16.
// ---------------------------------------------------------------------------
__global__ __launch_bounds__(256) void proj_mma(
    const float* __restrict__ bq, const float* __restrict__ bk,
    const float* __restrict__ bv, const float* __restrict__ bqr,
    const float* __restrict__ bkr)
{
    const int z = blockIdx.z;
    const __nv_bfloat16 *Ah, *Al;
    if (z < 3) { Ah = g_xh; Al = g_xl; } else { Ah = g_relh; Al = g_rell; }
    const __nv_bfloat16* Bh = g_Wh[z];
    const __nv_bfloat16* Bl = g_Wl[z];

    __nv_bfloat16 *Dh, *Dl; const float* bias;
    switch (z) {
        case 0:  Dh = g_qh;  Dl = g_ql;  bias = bq;  break;
        case 1:  Dh = g_kh;  Dl = g_kl;  bias = bk;  break;
        case 2:  Dh = g_vTh; Dl = g_vTl; bias = bv;  break;
        case 3:  Dh = g_qrh; Dl = g_qrl; bias = bqr; break;
        default: Dh = g_krh; Dl = g_krl; bias = bkr; break;
    }

    const int brow = blockIdx.y * 128;
    const int bcol = blockIdx.x * 128;

    float acc[2][8][4] = {};
    gemm_core<8>(Ah + brow * D_, Al + brow * D_, D_,
                 Bh + bcol * D_, Bl + bcol * D_, D_, 32, acc);

    const int lane = threadIdx.x & 31, wid = threadIdx.x >> 5;
    const int wm = wid & 3, wn = wid >> 2;
    const bool vtrans = (z == 2);

#pragma unroll
    for (int mt = 0; mt < 2; mt++) {
#pragma unroll
        for (int nt = 0; nt < 8; nt++) {
            const int n = bcol + wn * 64 + nt * 8 + (lane & 3) * 2;
            const int h = n >> 6, d = n & 63;
            const float b0 = __ldg(&bias[n]), b1 = __ldg(&bias[n + 1]);
#pragma unroll
            for (int half = 0; half < 2; half++) {
                const int m = brow + wm * 32 + mt * 16 + (lane >> 2) + half * 8;
                const int bb = m >> 10, s = m & (S_ - 1);
                float v0 = acc[mt][nt][half * 2 + 0] + b0;
                float v1 = acc[mt][nt][half * 2 + 1] + b1;
                __nv_bfloat16 h0, l0, h1, l1;
                split1(v0, h0, l0); split1(v1, h1, l1);
                if (!vtrans) {
                    const int idx = ((bb * H_ + h) * S_ + s) * DH_ + d;
                    __nv_bfloat162 ph; ph.x = h0; ph.y = h1;
                    __nv_bfloat162 pl; pl.x = l0; pl.y = l1;
                    *(__nv_bfloat162*)(Dh + idx) = ph;
                    *(__nv_bfloat162*)(Dl + idx) = pl;
                } else {
                    const int idx = ((bb * H_ + h) * DH_ + d) * S_ + s;
                    Dh[idx] = h0; Dh[idx + S_] = h1;
                    Dl[idx] = l0; Dl[idx + S_] = l1;
                }
            }
        }
    }
}

// ---------------------------------------------------------------------------
// Kernel 2: score GEMMs (fp32 out). z = bh*3 + which.  K = 64.
// ---------------------------------------------------------------------------
__global__ __launch_bounds__(256) void scores_mma()
{
    const int z = blockIdx.z;
    const int bh = z / 3;
    const int which = z - bh * 3;
    const int ho = bh * S_ * DH_;

    const __nv_bfloat16 *Ah, *Al, *Bh, *Bl; float* O;
    if (which == 0)      { Ah = g_qh + ho;  Al = g_ql + ho;  Bh = g_kh + ho;  Bl = g_kl + ho;  O = g_c2c + bh * SS_; }
    else if (which == 1) { Ah = g_qh + ho;  Al = g_ql + ho;  Bh = g_krh + ho; Bl = g_krl + ho; O = g_c2p + bh * SS_; }
    else                 { Ah = g_qrh + ho; Al = g_qrl + ho; Bh = g_kh + ho;  Bl = g_kl + ho;  O = g_p2c + bh * SS_; }

    const int brow = blockIdx.y * 128;
    const int bcol = blockIdx.x * 128;

    float acc[2][8][4] = {};
    gemm_core<8>(Ah + brow * DH_, Al + brow * DH_, DH_,
                 Bh + bcol * DH_, Bl + bcol * DH_, DH_, 2, acc);

    const int lane = threadIdx.x & 31, wid = threadIdx.x >> 5;
    const int wm = wid & 3, wn = wid >> 2;
#pragma unroll
    for (int mt = 0; mt < 2; mt++) {
#pragma unroll
        for (int nt = 0; nt < 8; nt++) {
            const int n = bcol + wn * 64 + nt * 8 + (lane & 3) * 2;
#pragma unroll
            for (int half = 0; half < 2; half++) {
                const int m = brow + wm * 32 + mt * 16 + (lane >> 2) + half * 8;
                *(float2*)(O + m * S_ + n) =
                    make_float2(acc[mt][nt][half * 2], acc[mt][nt][half * 2 + 1]);
            }
        }
    }
}

// ---------------------------------------------------------------------------
// Combine: 32 x 128 tile, exact-window band staging (scalar, coalesced,
// alignment-safe), float4 main loop.
// scores = (c2c + c2p[i, p(i,j)] + p2c[p(i,j), j]) / scale, + mask
// p(i,j) = clamp(i - j + 512, 0, 1023).
// c2pS[il][w]: w = 127 - jl  -> c2pS[il][w] = c2p[i0+il][clamp(P0+il-127+w)]
// p2cS[t][il]: t = il - jl + 127 -> p2c[clamp(P0-127+t)][j0 + il + 127 - t]
// ---------------------------------------------------------------------------
__global__ __launch_bounds__(256) void combine_kernel(const int* __restrict__ mask)
{
    const int bh = blockIdx.z;
    const int b  = bh >> 4;
    const int i0 = blockIdx.y * 32;
    const int j0 = blockIdx.x * 128;
    const int off = bh * SS_;
    const int P0 = i0 - j0 + 512;

    __shared__ float c2pS[32][132];   // pitch 132
    __shared__ float p2cS[159][33];   // pitch 33

    const int tid = threadIdx.x;

    // Stage c2p: row il needs p in [P0+il-127, P0+il]; scalar, coalesced.
    {
        const int row0 = tid >> 5;          // 0..7
        const int w0   = (tid & 31) * 4;    // 0..124 step 4  (4 consecutive per thread)
#pragma unroll
        for (int rr = 0; rr < 4; rr++) {
            const int row = row0 + rr * 8;
            const float* src = g_c2p + off + (i0 + row) * S_;
            const int pb = P0 + row - 127 + w0;
            float4 v;
            v.x = src[min(max(pb + 0, 0), S_ - 1)];
            v.y = src[min(max(pb + 1, 0), S_ - 1)];
            v.z = src[min(max(pb + 2, 0), S_ - 1)];
            v.w = src[min(max(pb + 3, 0), S_ - 1)];
            *(float4*)&c2pS[row][w0] = v;
        }
    }

    // Stage p2c: 159 t-rows x 32 slots, coalesced 32-wide per t-row.
#pragma unroll
    for (int it = 0; it < 20; it++) {
        const int seg = it * 256 + tid;
        if (seg < 159 * 32) {
            const int t  = seg >> 5;
            const int il = seg & 31;
            const int p  = min(max(P0 - 127 + t, 0), S_ - 1);
            const int j  = min(max(j0 + il + 127 - t, 0), S_ - 1);
            p2cS[t][il] = g_p2c[off + p * S_ + j];
        }
    }
    __syncthreads();

    const float invScale = 0.07216878364870323f;  // 1/sqrt(3*64)
    const int il = tid >> 3;
    const int jc = (tid & 7) * 4;
    float* crow = g_c2c + off + (i0 + il) * S_ + j0;
    const int* mrow = mask + b * S_ + j0;

#pragma unroll
    for (int pass = 0; pass < 4; pass++) {
        const int jl = jc + pass * 32;
        float4 c  = *(const float4*)(crow + jl);
        float4 cp = *(const float4*)&c2pS[il][124 - jl];   // reversed order
        const int tb = il - jl + 127;
        const float q0 = p2cS[tb    ][il];
        const float q1 = p2cS[tb - 1][il];
        const float q2 = p2cS[tb - 2][il];
        const float q3 = p2cS[tb - 3][il];
        const int4 mk = *(const int4*)(mrow + jl);

        float4 r;
        r.x = mk.x ? NEG_INF : (c.x + cp.w + q0) * invScale;
        r.y = mk.y ? NEG_INF : (c.y + cp.z + q1) * invScale;
        r.z = mk.z ? NEG_INF : (c.z + cp.y + q2) * invScale;
        r.w = mk.w ? NEG_INF : (c.w + cp.x + q3) * invScale;
        *(float4*)(crow + jl) = r;
    }
}

// ---------------------------------------------------------------------------
// Softmax: read fp32 scores, write probs as hi/lo bf16.
// ---------------------------------------------------------------------------
__global__ __launch_bounds__(256) void softmax_kernel()
{
    const int rowoff = blockIdx.y * SS_ + blockIdx.x * S_;
    const float* p = g_c2c + rowoff;
    const int tid = threadIdx.x;

    float4 v = *(const float4*)(p + tid * 4);
    float mx = fmaxf(fmaxf(v.x, v.y), fmaxf(v.z, v.w));
#pragma unroll
    for (int o = 16; o > 0; o >>= 1)
        mx = fmaxf(mx, __shfl_xor_sync(0xffffffffu, mx, o));

    __shared__ float smax[8], ssum[8];
    if ((tid & 31) == 0) smax[tid >> 5] = mx;
    __syncthreads();
    mx = fmaxf(fmaxf(fmaxf(smax[0], smax[1]), fmaxf(smax[2], smax[3])),
               fmaxf(fmaxf(smax[4], smax[5]), fmaxf(smax[6], smax[7])));

    v.x = __expf(v.x - mx);
    v.y = __expf(v.y - mx);
    v.z = __expf(v.z - mx);
    v.w = __expf(v.w - mx);
    float s = v.x + v.y + v.z + v.w;
#pragma unroll
    for (int o = 16; o > 0; o >>= 1)
        s += __shfl_xor_sync(0xffffffffu, s, o);
    if ((tid & 31) == 0) ssum[tid >> 5] = s;
    __syncthreads();
    s = ssum[0] + ssum[1] + ssum[2] + ssum[3] +
        ssum[4] + ssum[5] + ssum[6] + ssum[7];

    const float inv = 1.0f / s;
    v.x *= inv; v.y *= inv; v.z *= inv; v.w *= inv;

    __nv_bfloat16 h[4], l[4];
    split1(v.x, h[0], l[0]); split1(v.y, h[1], l[1]);
    split1(v.z, h[2], l[2]); split1(v.w, h[3], l[3]);
    *(uint2*)(g_ph + rowoff + tid * 4) = *(uint2*)h;
    *(uint2*)(g_pl + rowoff + tid * 4) = *(uint2*)l;
}

// ---------------------------------------------------------------------------
// Kernel 3: attn @ V  (probs 1024x1024 @ V 1024x64 per bh) -> ctx hi/lo bf16
// ---------------------------------------------------------------------------
__global__ __launch_bounds__(256) void av_mma()
{
    const int bh = blockIdx.y;
    const int i0 = blockIdx.x * 128;
    const __nv_bfloat16* Ah = g_ph + bh * SS_ + i0 * S_;
    const __nv_bfloat16* Al = g_pl + bh * SS_ + i0 * S_;
    const __nv_bfloat16* Bh = g_vTh + bh * DH_ * S_;
    const __nv_bfloat16* Bl = g_vTl + bh * DH_ * S_;

    float acc[2][4][4] = {};
    gemm_core<4>(Ah, Al, S_, Bh, Bl, S_, 32, acc);

    const int lane = threadIdx.x & 31, wid = threadIdx.x >> 5;
    const int wm = wid & 3, wn = wid >> 2;
    const int b = bh >> 4, h = bh & 15;

#pragma unroll
    for (int mt = 0; mt < 2; mt++) {
#pragma unroll
        for (int nt = 0; nt < 4; nt++) {
            const int d = wn * 32 + nt * 8 + (lane & 3) * 2;
#pragma unroll
            for (int half = 0; half < 2; half++) {
                const int s = i0 + wm * 32 + mt * 16 + (lane >> 2) + half * 8;
                const int idx = (b * S_ + s) * D_ + h * DH_ + d;
                float v0 = acc[mt][nt][half * 2 + 0];
                float v1 = acc[mt][nt][half * 2 + 1];
                __nv_bfloat16 h0, l0, h1, l1;
                split1(v0, h0, l0); split1(v1, h1, l1);
                __nv_bfloat162 ph; ph.x = h0; ph.y = h1;
                __nv_bfloat162 pl; pl.x = l0; pl.y = l1;
                *(__nv_bfloat162*)(g_ctxh + idx) = ph;
                *(__nv_bfloat162*)(g_ctxl + idx) = pl;
            }
        }
    }
}

// ---------------------------------------------------------------------------
// Kernel 4: output projection out = ctx @ Wc^T + bc  (fp32 out)
// ---------------------------------------------------------------------------
__global__ __launch_bounds__(256) void final_mma(
    const float* __restrict__ bc, float* __restrict__ out)
{
    const int brow = blockIdx.y * 128;
    const int bcol = blockIdx.x * 128;

    float acc[2][8][4] = {};
    gemm_core<8>(g_ctxh + brow * D_, g_ctxl + brow * D_, D_,
                 g_Wh[5] + bcol * D_, g_Wl[5] + bcol * D_, D_, 32, acc);

    const int lane = threadIdx.x & 31, wid = threadIdx.x >> 5;
    const int wm = wid & 3, wn = wid >> 2;
#pragma unroll
    for (int mt = 0; mt < 2; mt++) {
#pragma unroll
        for (int nt = 0; nt < 8; nt++) {
            const int n = bcol + wn * 64 + nt * 8 + (lane & 3) * 2;
            const float b0 = __ldg(&bc[n]), b1 = __ldg(&bc[n + 1]);
#pragma unroll
            for (int half = 0; half < 2; half++) {
                const int m = brow + wm * 32 + mt * 16 + (lane >> 2) + half * 8;
                *(float2*)(out + m * D_ + n) =
                    make_float2(acc[mt][nt][half * 2] + b0,
                                acc[mt][nt][half * 2 + 1] + b1);
            }
        }
    }
}

// ---------------------------------------------------------------------------
// Launch
// ---------------------------------------------------------------------------
extern "C" void kernel_launch(void* const* d_in, const int* in_sizes, int n_in,
                              void* d_out, int out_size)
{
    const float* x    = (const float*)d_in[0];
    const float* rel  = (const float*)d_in[1];
    const int*   mask = (const int*)  d_in[2];
    const float* Wq   = (const float*)d_in[3];
    const float* bq   = (const float*)d_in[4];
    const float* Wk   = (const float*)d_in[5];
    const float* bk   = (const float*)d_in[6];
    const float* Wv   = (const float*)d_in[7];
    const float* bv   = (const float*)d_in[8];
    const float* Wqr  = (const float*)d_in[9];
    const float* bqr  = (const float*)d_in[10];
    const float* Wkr  = (const float*)d_in[11];
    const float* bkr  = (const float*)d_in[12];
    const float* Wc   = (const float*)d_in[13];
    const float* bc   = (const float*)d_in[14];
    float* out = (float*)d_out;

    static int attr_done = 0;
    if (!attr_done) {
        cudaFuncSetAttribute(proj_mma,   cudaFuncAttributeMaxDynamicSharedMemorySize, SMEM_NT8);
        cudaFuncSetAttribute(scores_mma, cudaFuncAttributeMaxDynamicSharedMemorySize, SMEM_NT8);
        cudaFuncSetAttribute(av_mma,     cudaFuncAttributeMaxDynamicSharedMemorySize, SMEM_NT4);
        cudaFuncSetAttribute(final_mma,  cudaFuncAttributeMaxDynamicSharedMemorySize, SMEM_NT8);
        attr_done = 1;
    }

    // 0. Split fp32 operands into hi/lo bf16 (single launch)
    convert_all<<<2621440 / 256, 256>>>(x, rel, Wq, Wk, Wv, Wqr, Wkr, Wc);

    // 1. Projections (HMMA, z-fused)
    proj_mma<<<dim3(D_ / 128, ROWS_ / 128, 5), 256, SMEM_NT8>>>(bq, bk, bv, bqr, bkr);

    // 2. Score GEMMs
    scores_mma<<<dim3(S_ / 128, S_ / 128, BH_ * 3), 256, SMEM_NT8>>>();

    // 3. Banded gather + sum + scale + mask (32x128 tiles, vectorized)
    combine_kernel<<<dim3(S_ / 128, S_ / 32, BH_), 256>>>(mask);

    // 4. Softmax -> probs hi/lo bf16
    softmax_kernel<<<dim3(S_, BH_), 256>>>();

    // 5. attn @ V -> ctx hi/lo bf16
    av_mma<<<dim3(S_ / 128, BH_), 256, SMEM_NT4>>>();

    // 6. Output projection
    final_mma<<<dim3(D_ / 128, ROWS_ / 128), 256, SMEM_NT8>>>(bc, out);
}